// round 3
// baseline (speedup 1.0000x reference)
#include <cuda_runtime.h>
#include <cstdint>

#define S_LEN 2048
#define D_MODEL 2048
#define NB 2
#define NH 16
#define DHD 128
#define M_ROWS (NB * S_LEN) /* 4096 */
#define KDIM D_MODEL

// ---------------- scratch (static __device__, allocation-guard safe) -------
__device__ float g_q[(size_t)NB * NH * S_LEN * DHD];   // [b][h][s][d]
__device__ float g_k[(size_t)NB * NH * S_LEN * DHD];
__device__ float g_v[(size_t)NB * NH * S_LEN * DHD];
__device__ float g_ao[(size_t)M_ROWS * D_MODEL];       // [b*s][h*128+d]

// ---------------- tf32 helpers --------------------------------------------
__device__ __forceinline__ uint32_t f2tf(float x) {
    uint32_t r;
    asm("cvt.rna.tf32.f32 %0, %1;" : "=r"(r) : "f"(x));
    return r;
}

__device__ __forceinline__ void mma8(float c[4], const uint32_t a[4], const uint32_t b[2]) {
    asm volatile(
        "mma.sync.aligned.m16n8k8.row.col.f32.tf32.tf32.f32 "
        "{%0,%1,%2,%3}, {%4,%5,%6,%7}, {%8,%9}, {%0,%1,%2,%3};"
        : "+f"(c[0]), "+f"(c[1]), "+f"(c[2]), "+f"(c[3])
        : "r"(a[0]), "r"(a[1]), "r"(a[2]), "r"(a[3]), "r"(b[0]), "r"(b[1]));
}

// ---------------- GEMM: C[M,N] = A[M,K] @ W[N,K]^T -------------------------
// block tile 128x128, BK=32, 256 threads (8 warps, 2x4), warp tile 64x32.
// mode 0: RoPE -> g_q   mode 1: RoPE -> g_k   mode 2: plain -> g_v
// mode 3 (is_final): A = g_ao, plain row-major -> Oout (d_out)
__global__ __launch_bounds__(256) void gemm_tf32_kernel(
    const float* __restrict__ A_in,
    const float* __restrict__ W0, const float* __restrict__ W1,
    const float* __restrict__ W2,
    float* __restrict__ Oout,
    const float* __restrict__ fc, const float* __restrict__ fs,
    int is_final)
{
    __shared__ __align__(16) float As[128][36];
    __shared__ __align__(16) float Bs[128][36];

    const int mode = is_final ? 3 : (int)blockIdx.z;
    const float* A = is_final ? g_ao : A_in;
    const float* Wm = (mode == 1) ? W1 : (mode == 2) ? W2 : W0;

    const int tid  = threadIdx.x;
    const int warp = tid >> 5, lane = tid & 31;
    const int wm = warp >> 2, wn = warp & 3;     // 2 x 4 warp grid
    const int g  = lane >> 2, tg = lane & 3;

    const int bm = blockIdx.y, bn = blockIdx.x;

    float acc[4][4][4];
#pragma unroll
    for (int mi = 0; mi < 4; mi++)
#pragma unroll
        for (int ni = 0; ni < 4; ni++)
#pragma unroll
            for (int j = 0; j < 4; j++) acc[mi][ni][j] = 0.f;

    const float* Ablk = A  + (size_t)(bm * 128) * KDIM;
    const float* Bblk = Wm + (size_t)(bn * 128) * KDIM;

    for (int k0 = 0; k0 < KDIM; k0 += 32) {
#pragma unroll
        for (int i = 0; i < 4; i++) {
            int li = tid + i * 256;          // 0..1023 float4 slots
            int r  = li >> 3;                // 8 float4 per 32-col row
            int c4 = (li & 7) << 2;
            float4 va = *(const float4*)(Ablk + (size_t)r * KDIM + k0 + c4);
            *(float4*)(&As[r][c4]) = va;
            float4 vb = *(const float4*)(Bblk + (size_t)r * KDIM + k0 + c4);
            *(float4*)(&Bs[r][c4]) = vb;
        }
        __syncthreads();

#pragma unroll
        for (int kk = 0; kk < 4; kk++) {
            const int kc = kk * 8 + tg;
            uint32_t af[4][4], bf[4][2];
#pragma unroll
            for (int mi = 0; mi < 4; mi++) {
                int r0 = wm * 64 + mi * 16 + g;
                af[mi][0] = f2tf(As[r0][kc]);
                af[mi][1] = f2tf(As[r0 + 8][kc]);
                af[mi][2] = f2tf(As[r0][kc + 4]);
                af[mi][3] = f2tf(As[r0 + 8][kc + 4]);
            }
#pragma unroll
            for (int ni = 0; ni < 4; ni++) {
                int n0 = wn * 32 + ni * 8 + g;
                bf[ni][0] = f2tf(Bs[n0][kc]);
                bf[ni][1] = f2tf(Bs[n0][kc + 4]);
            }
#pragma unroll
            for (int mi = 0; mi < 4; mi++)
#pragma unroll
                for (int ni = 0; ni < 4; ni++)
                    mma8(acc[mi][ni], af[mi], bf[ni]);
        }
        __syncthreads();
    }

    // ---- epilogue ----
#pragma unroll
    for (int mi = 0; mi < 4; mi++) {
#pragma unroll
        for (int ni = 0; ni < 4; ni++) {
            int m0 = bm * 128 + wm * 64 + mi * 16 + g;
            int n0 = bn * 128 + wn * 32 + ni * 8 + tg * 2;
#pragma unroll
            for (int h2 = 0; h2 < 2; h2++) {
                int m = m0 + h2 * 8;
                float e = acc[mi][ni][h2 * 2];
                float o = acc[mi][ni][h2 * 2 + 1];
                if (mode == 3) {
                    *(float2*)(Oout + (size_t)m * D_MODEL + n0) = make_float2(e, o);
                } else {
                    int b = m >> 11, s = m & 2047;
                    int hh = n0 >> 7, d = n0 & 127;
                    if (mode != 2) {  // RoPE for Q, K
                        float c  = fc[s * 64 + (d >> 1)];
                        float sn = fs[s * 64 + (d >> 1)];
                        float e2 = e * c - o * sn;
                        float o2 = e * sn + o * c;
                        e = e2; o = o2;
                    }
                    size_t idx = ((size_t)(b * NH + hh) * S_LEN + s) * DHD + d;
                    float* dst = (mode == 0) ? g_q : (mode == 1) ? g_k : g_v;
                    *(float2*)(dst + idx) = make_float2(e, o);
                }
            }
        }
    }
}

// ---------------- Flash attention ------------------------------------------
// Block: (qb, bh). 256 threads, 8 warps x 16 q-rows. BQ=128, BKV=64.
// Q fragments live in registers (pre-scaled by 1/sqrt(128)).
#define KPAD 132
#define PPAD 68
#define ATT_SMEM ((2 * 64 * KPAD + 8 * 16 * PPAD) * 4) /* 102400 bytes */

__global__ __launch_bounds__(256) void attn_flash_kernel(float* __restrict__ out)
{
    extern __shared__ float smem_raw[];
    float (*Ks)[KPAD] = reinterpret_cast<float(*)[KPAD]>(smem_raw);
    float (*Vs)[KPAD] = reinterpret_cast<float(*)[KPAD]>(smem_raw + 64 * KPAD);
    float (*Ps)[PPAD] = reinterpret_cast<float(*)[PPAD]>(smem_raw + 2 * 64 * KPAD);

    const int bh = blockIdx.y;       // b*16 + h
    const int qb = blockIdx.x;       // q tile of 128
    const int tid = threadIdx.x;
    const int warp = tid >> 5, lane = tid & 31;
    const int g = lane >> 2, tg = lane & 3;
    const int r0 = qb * 128 + warp * 16 + g;  // global q row (second: +8)

    const float* qbase = g_q + (size_t)bh * S_LEN * DHD;
    const float* kbase = g_k + (size_t)bh * S_LEN * DHD;
    const float* vbase = g_v + (size_t)bh * S_LEN * DHD;

    const float scale = 0.08838834764831845f;  // 1/sqrt(128)

    // Q fragments for the whole DH=128 (16 k-steps of 8), scale folded in.
    uint32_t qf[16][4];
#pragma unroll
    for (int kk = 0; kk < 16; kk++) {
        int c = kk * 8 + tg;
        qf[kk][0] = f2tf(qbase[(size_t)r0 * DHD + c] * scale);
        qf[kk][1] = f2tf(qbase[(size_t)(r0 + 8) * DHD + c] * scale);
        qf[kk][2] = f2tf(qbase[(size_t)r0 * DHD + c + 4] * scale);
        qf[kk][3] = f2tf(qbase[(size_t)(r0 + 8) * DHD + c + 4] * scale);
    }

    float oacc[16][4];
#pragma unroll
    for (int ni = 0; ni < 16; ni++)
#pragma unroll
        for (int j = 0; j < 4; j++) oacc[ni][j] = 0.f;

    float m0v = -1e30f, m1v = -1e30f, l0 = 0.f, l1 = 0.f;

    const int nkv = 2 * (qb + 1);  // 64-wide kv tiles covering the causal range
    for (int t = 0; t < nkv; t++) {
        const int kv0 = t * 64;
        __syncthreads();
        // cooperative load of K,V tiles (64 x 128 each)
#pragma unroll
        for (int i = 0; i < 8; i++) {
            int li = tid + i * 256;          // 0..2047 float4 slots
            int r  = li >> 5;                // 32 float4 per row
            int c4 = (li & 31) << 2;
            *(float4*)(&Ks[r][c4]) = *(const float4*)(kbase + (size_t)(kv0 + r) * DHD + c4);
            *(float4*)(&Vs[r][c4]) = *(const float4*)(vbase + (size_t)(kv0 + r) * DHD + c4);
        }
        __syncthreads();

        if (kv0 <= qb * 128 + warp * 16 + 15) {   // warp has unmasked work
            // ---- scores: S = Q K^T (already scaled) ----
            float s[8][4];
#pragma unroll
            for (int ni = 0; ni < 8; ni++)
#pragma unroll
                for (int j = 0; j < 4; j++) s[ni][j] = 0.f;

#pragma unroll
            for (int kk = 0; kk < 16; kk++) {
                const int kc = kk * 8 + tg;
#pragma unroll
                for (int ni = 0; ni < 8; ni++) {
                    uint32_t bf[2];
                    bf[0] = f2tf(Ks[ni * 8 + g][kc]);
                    bf[1] = f2tf(Ks[ni * 8 + g][kc + 4]);
                    mma8(s[ni], qf[kk], bf);
                }
            }

            // ---- causal mask + tile max ----
            float mn0 = -1e30f, mn1 = -1e30f;
#pragma unroll
            for (int ni = 0; ni < 8; ni++) {
                int c = kv0 + ni * 8 + tg * 2;
                if (c > r0)         s[ni][0] = -1e30f;
                if (c + 1 > r0)     s[ni][1] = -1e30f;
                if (c > r0 + 8)     s[ni][2] = -1e30f;
                if (c + 1 > r0 + 8) s[ni][3] = -1e30f;
                mn0 = fmaxf(mn0, fmaxf(s[ni][0], s[ni][1]));
                mn1 = fmaxf(mn1, fmaxf(s[ni][2], s[ni][3]));
            }
            mn0 = fmaxf(mn0, __shfl_xor_sync(0xffffffffu, mn0, 1));
            mn0 = fmaxf(mn0, __shfl_xor_sync(0xffffffffu, mn0, 2));
            mn1 = fmaxf(mn1, __shfl_xor_sync(0xffffffffu, mn1, 1));
            mn1 = fmaxf(mn1, __shfl_xor_sync(0xffffffffu, mn1, 2));

            float mt0 = fmaxf(m0v, mn0), mt1 = fmaxf(m1v, mn1);
            float a0 = __expf(m0v - mt0), a1 = __expf(m1v - mt1);
            m0v = mt0; m1v = mt1;

            // ---- exp + P to per-warp smem ----
            float rs0 = 0.f, rs1 = 0.f;
#pragma unroll
            for (int ni = 0; ni < 8; ni++) {
                float p0 = __expf(s[ni][0] - mt0);
                float p1 = __expf(s[ni][1] - mt0);
                float p2 = __expf(s[ni][2] - mt1);
                float p3 = __expf(s[ni][3] - mt1);
                rs0 += p0 + p1;
                rs1 += p2 + p3;
                int cc = ni * 8 + tg * 2;
                *(float2*)(&Ps[(warp << 4) + g][cc])     = make_float2(p0, p1);
                *(float2*)(&Ps[(warp << 4) + g + 8][cc]) = make_float2(p2, p3);
            }
            rs0 += __shfl_xor_sync(0xffffffffu, rs0, 1);
            rs0 += __shfl_xor_sync(0xffffffffu, rs0, 2);
            rs1 += __shfl_xor_sync(0xffffffffu, rs1, 1);
            rs1 += __shfl_xor_sync(0xffffffffu, rs1, 2);
            l0 = l0 * a0 + rs0;
            l1 = l1 * a1 + rs1;

            // rescale running output
#pragma unroll
            for (int ni = 0; ni < 16; ni++) {
                oacc[ni][0] *= a0; oacc[ni][1] *= a0;
                oacc[ni][2] *= a1; oacc[ni][3] *= a1;
            }
            __syncwarp();

            // ---- O += P @ V ----
#pragma unroll
            for (int kk2 = 0; kk2 < 8; kk2++) {
                const int kc = kk2 * 8 + tg;
                uint32_t af[4];
                af[0] = f2tf(Ps[(warp << 4) + g][kc]);
                af[1] = f2tf(Ps[(warp << 4) + g + 8][kc]);
                af[2] = f2tf(Ps[(warp << 4) + g][kc + 4]);
                af[3] = f2tf(Ps[(warp << 4) + g + 8][kc + 4]);
#pragma unroll
                for (int ni2 = 0; ni2 < 16; ni2++) {
                    uint32_t bf[2];
                    bf[0] = f2tf(Vs[kc][ni2 * 8 + g]);
                    bf[1] = f2tf(Vs[kc + 4][ni2 * 8 + g]);
                    mma8(oacc[ni2], af, bf);
                }
            }
        }
    }

    // ---- epilogue: divide by l, write [b][s][h*128+d] ----
    const int b = bh >> 4, h = bh & 15;
    const float inv0 = 1.f / l0, inv1 = 1.f / l1;
#pragma unroll
    for (int ni2 = 0; ni2 < 16; ni2++) {
        int d = ni2 * 8 + tg * 2;
        size_t i0 = ((size_t)b * S_LEN + r0) * D_MODEL + h * DHD + d;
        size_t i1 = ((size_t)b * S_LEN + r0 + 8) * D_MODEL + h * DHD + d;
        *(float2*)(out + i0) = make_float2(oacc[ni2][0] * inv0, oacc[ni2][1] * inv0);
        *(float2*)(out + i1) = make_float2(oacc[ni2][2] * inv1, oacc[ni2][3] * inv1);
    }
}

// ---------------- launch ----------------------------------------------------
extern "C" void kernel_launch(void* const* d_in, const int* in_sizes, int n_in,
                              void* d_out, int out_size)
{
    (void)in_sizes; (void)n_in; (void)out_size;
    const float* x  = (const float*)d_in[0];
    const float* fc = (const float*)d_in[1];
    const float* fs = (const float*)d_in[2];
    // d_in[3] = mask (causal, implemented analytically)
    const float* wq = (const float*)d_in[4];
    const float* wk = (const float*)d_in[5];
    const float* wv = (const float*)d_in[6];
    const float* wo = (const float*)d_in[7];
    float* out = (float*)d_out;

    dim3 blk(256);

    // 1) fused QKV projections + RoPE
    dim3 g1(D_MODEL / 128, M_ROWS / 128, 3);
    gemm_tf32_kernel<<<g1, blk>>>(x, wq, wk, wv, out, fc, fs, 0);

    // 2) flash attention -> g_ao
    float* ao_ptr = nullptr;
    cudaGetSymbolAddress((void**)&ao_ptr, g_ao);
    cudaFuncSetAttribute(attn_flash_kernel,
                         cudaFuncAttributeMaxDynamicSharedMemorySize, ATT_SMEM);
    dim3 g2(S_LEN / 128, NB * NH);
    attn_flash_kernel<<<g2, blk, ATT_SMEM>>>(ao_ptr);

    // 3) output projection -> d_out
    dim3 g3(D_MODEL / 128, M_ROWS / 128, 1);
    gemm_tf32_kernel<<<g3, blk>>>(nullptr, wo, nullptr, nullptr, out, fc, fs, 1);
}